// round 7
// baseline (speedup 1.0000x reference)
#include <cuda_runtime.h>
#include <cuda_bf16.h>
#include <cstdint>
#include <cstddef>
#include <math.h>

#define N_FFT   16000
#define BATCH   512
#define D_IN    2048
#define ODIM    3000
#define OPAD    3072
#define KDIM    16000

// Scratch (device globals — allocation-free per harness rules)
__device__ float2 g_CBUF[BATCH * N_FFT];                       // 64 MB
__device__ float2 g_TW[N_FFT];                                 // twiddles
__device__ __align__(16) __nv_bfloat16 g_Zhi[BATCH * KDIM];    // 16 MB
__device__ __align__(16) __nv_bfloat16 g_Zlo[BATCH * KDIM];    // 16 MB
__device__ __align__(16) __nv_bfloat16 g_Whi[OPAD * KDIM];     // 98 MB
__device__ __align__(16) __nv_bfloat16 g_Wlo[OPAD * KDIM];     // 98 MB

static __device__ __forceinline__ float2 cmulf(float2 a, float2 b) {
    return make_float2(a.x * b.x - a.y * b.y, a.x * b.y + a.y * b.x);
}
static __device__ __forceinline__ unsigned smem_u32(const void* p) {
    unsigned a;
    asm("{ .reg .u64 t; cvta.to.shared.u64 t, %1; cvt.u32.u64 %0, t; }" : "=r"(a) : "l"(p));
    return a;
}
static __device__ __forceinline__ unsigned swz128(unsigned off) {
    return off ^ ((off >> 3) & 0x70);
}
#define CP_ASYNC16(dst, src) \
    asm volatile("cp.async.cg.shared.global [%0], [%1], 16;" :: "r"(dst), "l"(src))
#define CP_COMMIT() asm volatile("cp.async.commit_group;" ::: "memory")
#define CP_WAIT1()  asm volatile("cp.async.wait_group 1;" ::: "memory")

static __device__ __forceinline__ void ldsm_x4(unsigned addr, unsigned* r) {
    asm volatile("ldmatrix.sync.aligned.m8n8.x4.shared.b16 {%0,%1,%2,%3}, [%4];"
                 : "=r"(r[0]), "=r"(r[1]), "=r"(r[2]), "=r"(r[3]) : "r"(addr));
}
static __device__ __forceinline__ void mma_bf16(float* c, const unsigned* a, const unsigned* b) {
    asm volatile(
        "mma.sync.aligned.m16n8k16.row.col.f32.bf16.bf16.f32 "
        "{%0,%1,%2,%3}, {%4,%5,%6,%7}, {%8,%9}, {%0,%1,%2,%3};"
        : "+f"(c[0]), "+f"(c[1]), "+f"(c[2]), "+f"(c[3])
        : "r"(a[0]), "r"(a[1]), "r"(a[2]), "r"(a[3]), "r"(b[0]), "r"(b[1]));
}
static __device__ __forceinline__ void bf16_split(float x, __nv_bfloat16& h, __nv_bfloat16& l) {
    h = __float2bfloat16_rn(x);
    l = __float2bfloat16_rn(x - __bfloat162float(h));
}

// ---------------------------------------------------------------------------
__global__ void tw_init_kernel() {
    int j = blockIdx.x * blockDim.x + threadIdx.x;
    if (j < N_FFT) {
        double ang = -2.0 * 3.14159265358979323846 * (double)j / (double)N_FFT;
        double s, c;
        sincos(ang, &s, &c);
        g_TW[j] = make_float2((float)c, (float)s);
    }
}

__global__ void zero_cbuf_kernel() {
    int i = blockIdx.x * blockDim.x + threadIdx.x;
    const int n4 = BATCH * N_FFT * 2 / 4;
    if (i < n4) {
        reinterpret_cast<float4*>(g_CBUF)[i] = make_float4(0.f, 0.f, 0.f, 0.f);
    }
}

// W -> bf16 hi/lo planes (rows >= ODIM zero-filled)
__global__ void wconv_kernel(const float* __restrict__ Wm) {
    int lin = blockIdx.x * blockDim.x + threadIdx.x;      // one float4 per thread
    const int SEGS = KDIM / 4;                            // 4000
    if (lin >= OPAD * SEGS) return;
    int r = lin / SEGS;
    int s = lin - r * SEGS;
    float4 v = (r < ODIM) ? *reinterpret_cast<const float4*>(Wm + (size_t)r * KDIM + s * 4)
                          : make_float4(0.f, 0.f, 0.f, 0.f);
    __nv_bfloat16 h0, l0, h1, l1, h2, l2, h3, l3;
    bf16_split(v.x, h0, l0);
    bf16_split(v.y, h1, l1);
    bf16_split(v.z, h2, l2);
    bf16_split(v.w, h3, l3);
    size_t off = (size_t)r * KDIM + s * 4;
    unsigned hA = ((unsigned)__bfloat16_as_ushort(h1) << 16) | __bfloat16_as_ushort(h0);
    unsigned hB = ((unsigned)__bfloat16_as_ushort(h3) << 16) | __bfloat16_as_ushort(h2);
    unsigned lA = ((unsigned)__bfloat16_as_ushort(l1) << 16) | __bfloat16_as_ushort(l0);
    unsigned lB = ((unsigned)__bfloat16_as_ushort(l3) << 16) | __bfloat16_as_ushort(l2);
    *reinterpret_cast<uint2*>(g_Whi + off) = make_uint2(hA, hB);
    *reinterpret_cast<uint2*>(g_Wlo + off) = make_uint2(lA, lB);
}

// ---------------------------------------------------------------------------
// Count sketch (packed complex c = p1 + i*p2)
// ---------------------------------------------------------------------------
__global__ void sketch_kernel(const float* __restrict__ x0, const float* __restrict__ x1,
                              const float* __restrict__ s1, const float* __restrict__ s2,
                              const int* __restrict__ h1, const int* __restrict__ h2) {
    int idx = blockIdx.x * blockDim.x + threadIdx.x;
    if (idx >= BATCH * D_IN) return;
    int b = idx / D_IN;
    int a = idx - b * D_IN;
    float v1 = s1[a] * x0[idx];
    float v2 = s2[a] * x1[idx];
    float2* row = g_CBUF + (size_t)b * N_FFT;
    atomicAdd(&row[h1[a]].x, v1);
    atomicAdd(&row[h2[a]].y, v2);
}

// ---------------------------------------------------------------------------
// 16000-pt complex FFT, one CTA per batch row, whole row in smem.
// N = 128 * 125.  Step A: radix-2 x7 (chunk q -> k1=bitrev7(q));
// Step B: twiddle; Step C: radix-5 x3 (slot j -> k2=rev5(j)).
// Output phase GATHERS from smem so global stores are linear/coalesced.
// ---------------------------------------------------------------------------
template <bool INV>
__global__ __launch_bounds__(512) void fft_kernel() {
    extern __shared__ float2 sm[];
    float2* A    = sm;            // 16000
    float2* W125 = sm + N_FFT;    // 125

    const int b   = blockIdx.x;
    const int tid = threadIdx.x;
    const int T   = blockDim.x;   // 512
    float2* row = g_CBUF + (size_t)b * N_FFT;

    // ---- load phase ----
    if (!INV) {
        for (int k = tid; k < N_FFT; k += T) A[k] = row[k];
    } else {
        for (int k = tid; k < N_FFT; k += T) {
            float2 C = row[k];
            float2 D = row[k == 0 ? 0 : N_FFT - k];
            float2 F1 = make_float2(0.5f * (C.x + D.x), 0.5f * (C.y - D.y));
            float2 F2 = make_float2(0.5f * (C.y + D.y), 0.5f * (D.x - C.x));
            A[k] = cmulf(F1, F2);
        }
    }
    for (int m = tid; m < 125; m += T) {
        float2 t = g_TW[128 * m];        // W_125^m
        if (INV) t.y = -t.y;
        W125[m] = t;
    }
    __syncthreads();

    // ---- Step A: radix-2 DIF, 7 stages ----
#pragma unroll
    for (int stage = 0; stage < 7; ++stage) {
        const int L = 128 >> stage;
        const int half = L >> 1;
        const int twstep = 125 << stage;
        for (int i = tid; i < 8000; i += T) {
            int n2 = i % 125;
            int t  = i / 125;
            int blk = t / half;
            int j   = t - blk * half;
            int p  = (blk * L + j) * 125 + n2;
            int p2 = p + half * 125;
            float2 u = A[p], v = A[p2];
            float2 tw = g_TW[j * twstep];
            if (INV) tw.y = -tw.y;
            A[p]  = make_float2(u.x + v.x, u.y + v.y);
            float2 d = make_float2(u.x - v.x, u.y - v.y);
            A[p2] = cmulf(d, tw);
        }
        __syncthreads();
    }

    // ---- Step B: twiddle W_N^{n2 * k1}, k1 = bitrev7(chunk) ----
    for (int p = tid; p < N_FFT; p += T) {
        int q  = p / 125;
        int n2 = p - q * 125;
        int k1 = __brev((unsigned)q) >> 25;
        float2 tw = g_TW[n2 * k1];
        if (INV) tw.y = -tw.y;
        A[p] = cmulf(A[p], tw);
    }
    __syncthreads();

    // ---- Step C: 3 radix-5 DIF stages per 125-chunk ----
    {
        const float c1 = 0.309016994374947424f;
        const float c2 = -0.809016994374947424f;
        const float S1 = INV ? -0.951056516295153572f : 0.951056516295153572f;
        const float S2 = INV ? -0.587785252292473129f : 0.587785252292473129f;
        const int Ls[3]   = {125, 25, 5};
        const int subs[3] = {25, 5, 1};
        const int fs[3]   = {1, 5, 25};
#pragma unroll
        for (int s = 0; s < 3; ++s) {
            const int L = Ls[s], sub = subs[s], f = fs[s];
            for (int i = tid; i < 3200; i += T) {
                int q = i / 25;
                int t = i - q * 25;
                int blk = t / sub;
                int j   = t - blk * sub;
                int base = q * 125 + blk * L + j;
                float2 x0 = A[base];
                float2 x1 = A[base + sub];
                float2 x2 = A[base + 2 * sub];
                float2 x3 = A[base + 3 * sub];
                float2 x4 = A[base + 4 * sub];
                float t1x = x1.x + x4.x, t1y = x1.y + x4.y;
                float t2x = x2.x + x3.x, t2y = x2.y + x3.y;
                float t3x = x1.x - x4.x, t3y = x1.y - x4.y;
                float t4x = x2.x - x3.x, t4y = x2.y - x3.y;
                float2 y0 = make_float2(x0.x + t1x + t2x, x0.y + t1y + t2y);
                float ax = x0.x + c1 * t1x + c2 * t2x;
                float ay = x0.y + c1 * t1y + c2 * t2y;
                float bx = S1 * t3x + S2 * t4x;
                float by = S1 * t3y + S2 * t4y;
                float dx = x0.x + c2 * t1x + c1 * t2x;
                float dy = x0.y + c2 * t1y + c1 * t2y;
                float ex = S2 * t3x - S1 * t4x;
                float ey = S2 * t3y - S1 * t4y;
                float2 y1 = make_float2(ax + by, ay - bx);
                float2 y4 = make_float2(ax - by, ay + bx);
                float2 y2 = make_float2(dx + ey, dy - ex);
                float2 y3 = make_float2(dx - ey, dy + ex);
                int jf = j * f;
                A[base]           = y0;
                A[base + sub]     = cmulf(y1, W125[jf]);
                A[base + 2 * sub] = cmulf(y2, W125[2 * jf]);
                A[base + 3 * sub] = cmulf(y3, W125[3 * jf]);
                A[base + 4 * sub] = cmulf(y4, W125[4 * jf]);
            }
            __syncthreads();
        }
    }

    // ---- output: gather from smem (digit-reversed source), store linearly ----
    const float invN = 1.0f / (float)N_FFT;
    for (int k = tid; k < N_FFT; k += T) {
        int k1 = k & 127;
        int k2 = k >> 7;
        int q = __brev((unsigned)k1) >> 25;                      // rev7 (involution)
        int j = (k2 % 5) * 25 + ((k2 / 5) % 5) * 5 + (k2 / 25);  // rev5 inverse
        float2 v = A[q * 125 + j];
        if (!INV) {
            row[k] = v;
        } else {
            float z = v.x * invN;
            __nv_bfloat16 h, l;
            bf16_split(z, h, l);
            g_Zhi[(size_t)b * KDIM + k] = h;
            g_Zlo[(size_t)b * KDIM + k] = l;
        }
    }
}

// ---------------------------------------------------------------------------
// HMMA bf16 3-term GEMM on preconverted planes:
//   out[512,3000] = relu(Z @ W^T + b); terms zhi*whi + zhi*wlo + zlo*whi.
// Tile 128x96, TK=64, grid (32,4)=128 CTAs, 256 thr, 3-stage cp.async pipe.
// Stage: Ahi 16K | Alo 16K | Bhi 12K | Blo 12K = 56 KB; 3 stages = 168 KB.
// ---------------------------------------------------------------------------
#define GTK 64
#define GITERS (KDIM / GTK)          // 250
#define A_PL 16384
#define B_PL 12288
#define STG_BYTES (2 * A_PL + 2 * B_PL)   // 57344
#define GEMM_SMEM (3 * STG_BYTES)         // 172032

static __device__ __forceinline__ void gemm_issue_stage(
    unsigned sb, const char* zhi, const char* zlo,
    const char* whi, const char* wlo, int tid, int k0, int m0, int n0g) {
    // A: 128 rows x 8 segs x 2 planes
#pragma unroll
    for (int i = 0; i < 4; ++i) {
        int lin = i * 256 + tid;
        int r = lin >> 3, seg = lin & 7;
        unsigned d = sb + swz128((unsigned)(r * 128 + seg * 16));
        size_t so = ((size_t)(m0 + r) * KDIM + k0 + seg * 8) * 2;
        CP_ASYNC16(d, zhi + so);
        CP_ASYNC16(d + A_PL, zlo + so);
    }
    // B: 96 rows x 8 segs x 2 planes
#pragma unroll
    for (int i = 0; i < 3; ++i) {
        int lin = i * 256 + tid;
        int r = lin >> 3, seg = lin & 7;
        unsigned d = sb + 2 * A_PL + swz128((unsigned)(r * 128 + seg * 16));
        size_t so = ((size_t)(n0g + r) * KDIM + k0 + seg * 8) * 2;
        CP_ASYNC16(d, whi + so);
        CP_ASYNC16(d + B_PL, wlo + so);
    }
}

__global__ __launch_bounds__(256, 1) void gemm_hmma_kernel(const float* __restrict__ bias,
                                                           float* __restrict__ out) {
    extern __shared__ char gsm[];
    const unsigned sbase = smem_u32(gsm);
    const int tid  = threadIdx.x;
    const int lane = tid & 31;
    const int wid  = tid >> 5;
    const int wm   = wid >> 1;          // 0..3 -> 32 m rows each
    const int wn   = wid & 1;           // 0..1 -> 48 n cols each
    const int n0 = blockIdx.x * 96;
    const int m0 = blockIdx.y * 128;

    const char* zhi = reinterpret_cast<const char*>(g_Zhi);
    const char* zlo = reinterpret_cast<const char*>(g_Zlo);
    const char* whi = reinterpret_cast<const char*>(g_Whi);
    const char* wlo = reinterpret_cast<const char*>(g_Wlo);

    float acc[2][6][4];
#pragma unroll
    for (int i = 0; i < 2; ++i)
#pragma unroll
        for (int j = 0; j < 6; ++j)
#pragma unroll
            for (int e = 0; e < 4; ++e) acc[i][j][e] = 0.f;

    gemm_issue_stage(sbase, zhi, zlo, whi, wlo, tid, 0, m0, n0);
    CP_COMMIT();
    gemm_issue_stage(sbase + STG_BYTES, zhi, zlo, whi, wlo, tid, GTK, m0, n0);
    CP_COMMIT();

    // precomputed fragment sub-offsets
    const unsigned aRowSel = (unsigned)(lane & 15) * 128 + ((unsigned)(lane >> 4) << 4);
    const unsigned bRowSel = (unsigned)((lane & 7) | (((lane >> 4) & 1) << 3)) * 128 +
                             (((unsigned)(lane >> 3) & 1) << 4);

    for (int c = 0; c < GITERS; ++c) {
        CP_WAIT1();
        __syncthreads();
        if (c + 2 < GITERS) {
            gemm_issue_stage(sbase + ((c + 2) % 3) * STG_BYTES,
                             zhi, zlo, whi, wlo, tid, (c + 2) * GTK, m0, n0);
        }
        CP_COMMIT();

        const unsigned Ab = sbase + (c % 3) * STG_BYTES;
        const unsigned Bb = Ab + 2 * A_PL;
#pragma unroll
        for (int ks = 0; ks < 4; ++ks) {
            unsigned Af[2][2][4];
            unsigned Bf[2][3][4];
#pragma unroll
            for (int p = 0; p < 2; ++p) {
#pragma unroll
                for (int mf = 0; mf < 2; ++mf) {
                    unsigned off = (unsigned)((wm * 32 + mf * 16) * 128 + ks * 32) + aRowSel;
                    ldsm_x4(Ab + p * A_PL + swz128(off), Af[p][mf]);
                }
#pragma unroll
                for (int g = 0; g < 3; ++g) {
                    unsigned off = (unsigned)((wn * 48 + g * 16) * 128 + ks * 32) + bRowSel;
                    ldsm_x4(Bb + p * B_PL + swz128(off), Bf[p][g]);
                }
            }
#pragma unroll
            for (int t = 0; t < 3; ++t) {
                const int ap = (t == 2) ? 1 : 0;
                const int bp = (t == 1) ? 1 : 0;
#pragma unroll
                for (int mf = 0; mf < 2; ++mf)
#pragma unroll
                    for (int nf = 0; nf < 6; ++nf)
                        mma_bf16(acc[mf][nf], Af[ap][mf], &Bf[bp][nf >> 1][(nf & 1) * 2]);
            }
        }
        __syncthreads();
    }

    // ---- epilogue: bias + relu ----
#pragma unroll
    for (int mf = 0; mf < 2; ++mf) {
        int mlo = m0 + wm * 32 + mf * 16 + (lane >> 2);
#pragma unroll
        for (int nf = 0; nf < 6; ++nf) {
            int n = n0 + wn * 48 + nf * 8 + 2 * (lane & 3);
            if (n < ODIM) {
                float b0 = bias[n], b1 = bias[n + 1];
                float2 v0, v1;
                v0.x = fmaxf(acc[mf][nf][0] + b0, 0.f);
                v0.y = fmaxf(acc[mf][nf][1] + b1, 0.f);
                v1.x = fmaxf(acc[mf][nf][2] + b0, 0.f);
                v1.y = fmaxf(acc[mf][nf][3] + b1, 0.f);
                *reinterpret_cast<float2*>(out + (size_t)mlo * ODIM + n) = v0;
                *reinterpret_cast<float2*>(out + (size_t)(mlo + 8) * ODIM + n) = v1;
            }
        }
    }
}

// ---------------------------------------------------------------------------
extern "C" void kernel_launch(void* const* d_in, const int* in_sizes, int n_in,
                              void* d_out, int out_size) {
    const float* x0  = (const float*)d_in[0];
    const float* x1  = (const float*)d_in[1];
    const float* s1  = (const float*)d_in[2];
    const float* s2  = (const float*)d_in[3];
    const float* Wm  = (const float*)d_in[4];
    const float* bia = (const float*)d_in[5];
    const int*   h1  = (const int*)d_in[6];
    const int*   h2  = (const int*)d_in[7];
    float* out = (float*)d_out;

    const int FFT_SMEM = (N_FFT + 128) * (int)sizeof(float2);  // 129 KB

    cudaFuncSetAttribute(fft_kernel<false>, cudaFuncAttributeMaxDynamicSharedMemorySize, FFT_SMEM);
    cudaFuncSetAttribute(fft_kernel<true>,  cudaFuncAttributeMaxDynamicSharedMemorySize, FFT_SMEM);
    cudaFuncSetAttribute(gemm_hmma_kernel, cudaFuncAttributeMaxDynamicSharedMemorySize, GEMM_SMEM);

    tw_init_kernel<<<(N_FFT + 255) / 256, 256>>>();

    const int n4 = BATCH * N_FFT * 2 / 4;
    zero_cbuf_kernel<<<(n4 + 255) / 256, 256>>>();

    sketch_kernel<<<(BATCH * D_IN + 255) / 256, 256>>>(x0, x1, s1, s2, h1, h2);

    const int wthreads = OPAD * (KDIM / 4);
    wconv_kernel<<<(wthreads + 255) / 256, 256>>>(Wm);

    fft_kernel<false><<<BATCH, 512, FFT_SMEM>>>();
    fft_kernel<true><<<BATCH, 512, FFT_SMEM>>>();

    gemm_hmma_kernel<<<dim3((ODIM + 95) / 96, BATCH / 128), 256, GEMM_SMEM>>>(bia, out);
}